// round 3
// baseline (speedup 1.0000x reference)
#include <cuda_runtime.h>
#include <cuda_bf16.h>

#define IN_F 256
#define HF   128
#define NC   64
#define MAX_NODES 10000
#define MAX_EDGES 640000
#define PAD 192   // max supported degree; Poisson(64) tail at 192 is ~1e-60

typedef unsigned long long ull;

// ---------------- f32x2 packed-math helpers (sm_103a) -------------------------
__device__ __forceinline__ ull pk2(float lo, float hi) {
    ull r; asm("mov.b64 %0, {%1, %2};" : "=l"(r) : "f"(lo), "f"(hi)); return r;
}
__device__ __forceinline__ void upk2(float& lo, float& hi, ull v) {
    asm("mov.b64 {%0, %1}, %2;" : "=f"(lo), "=f"(hi) : "l"(v));
}
#define FMA2(d, a, b, c) \
    asm("fma.rn.f32x2 %0, %1, %2, %3;" : "=l"(d) : "l"(a), "l"(b), "l"(c))
#define ADD2(d, a, b) \
    asm("add.rn.f32x2 %0, %1, %2;" : "=l"(d) : "l"(a), "l"(b))

// ---------------- scratch (static device globals; no allocation) -------------
__device__ float g_h0[MAX_NODES * HF];
__device__ float g_h1[MAX_NODES * HF];
__device__ float g_h2[MAX_NODES * HF];
__device__ float g_mean[MAX_NODES * HF];
__device__ int   g_cnt[MAX_NODES];
__device__ int   g_csr[MAX_NODES * PAD];
__device__ int   g_is64;

// ---------------- dtype detect -----------------------------------------------
__global__ void detect_kernel(const void* ei, long long total_elems, int n_nodes) {
    if (threadIdx.x == 0 && blockIdx.x == 0) g_is64 = 1;
    __threadfence();
    const long long* p = (const long long*)ei;
    long long nsamp = total_elems < 4096 ? total_elems : 4096;
    for (long long i = threadIdx.x; i < nsamp; i += blockDim.x) {
        long long v = p[i];
        if (v < 0 || v >= (long long)n_nodes) { g_is64 = 0; break; }
    }
}

// ---------------- padded-CSR scatter (one pass, no scan) ----------------------
__global__ void scatter_kernel(const void* ei, int E) {
    int e = blockIdx.x * blockDim.x + threadIdx.x;
    if (e >= E) return;
    int is64 = g_is64;
    int src, dst;
    if (is64) {
        src = (int)((const long long*)ei)[e];
        dst = (int)((const long long*)ei)[(long long)E + e];
    } else {
        src = ((const int*)ei)[e];
        dst = ((const int*)ei)[E + e];
    }
    int pos = atomicAdd(&g_cnt[dst], 1);
    if (pos < PAD) g_csr[dst * PAD + pos] = src;
}

// ---------------- mean aggregation (pull over padded CSR, warp per node) ------
// 4 independent accumulator chains (f32x2 packed), unroll 4 for MLP.
__global__ void __launch_bounds__(256, 4)
agg_kernel(const float* __restrict__ h, float* __restrict__ out, int n) {
    int warp = (blockIdx.x * blockDim.x + threadIdx.x) >> 5;
    int lane = threadIdx.x & 31;
    if (warp >= n) return;
    int deg = g_cnt[warp];
    int end = deg < PAD ? deg : PAD;
    const int* lst = &g_csr[warp * PAD];
    const ulonglong2* hb = (const ulonglong2*)h;   // float4 rows as packed pairs

    ull a0p0 = 0, a0p1 = 0, a1p0 = 0, a1p1 = 0;
    ull a2p0 = 0, a2p1 = 0, a3p0 = 0, a3p1 = 0;
    // zero-init packed (bit pattern 0 == (0.f,0.f))

    int e = 0;
    for (; e + 3 < end; e += 4) {
        int j0 = lst[e], j1 = lst[e + 1], j2 = lst[e + 2], j3 = lst[e + 3];
        ulonglong2 v0 = hb[(long long)j0 * (HF / 4) + lane];
        ulonglong2 v1 = hb[(long long)j1 * (HF / 4) + lane];
        ulonglong2 v2 = hb[(long long)j2 * (HF / 4) + lane];
        ulonglong2 v3 = hb[(long long)j3 * (HF / 4) + lane];
        ADD2(a0p0, a0p0, v0.x); ADD2(a0p1, a0p1, v0.y);
        ADD2(a1p0, a1p0, v1.x); ADD2(a1p1, a1p1, v1.y);
        ADD2(a2p0, a2p0, v2.x); ADD2(a2p1, a2p1, v2.y);
        ADD2(a3p0, a3p0, v3.x); ADD2(a3p1, a3p1, v3.y);
    }
    for (; e < end; e++) {
        int j0 = lst[e];
        ulonglong2 v0 = hb[(long long)j0 * (HF / 4) + lane];
        ADD2(a0p0, a0p0, v0.x); ADD2(a0p1, a0p1, v0.y);
    }
    ADD2(a0p0, a0p0, a1p0); ADD2(a0p1, a0p1, a1p1);
    ADD2(a2p0, a2p0, a3p0); ADD2(a2p1, a2p1, a3p1);
    ADD2(a0p0, a0p0, a2p0); ADD2(a0p1, a0p1, a2p1);

    float s = 1.0f / (float)(deg > 1 ? deg : 1);
    float f0, f1, f2, f3;
    upk2(f0, f1, a0p0);
    upk2(f2, f3, a0p1);
    float4 r = make_float4(f0 * s, f1 * s, f2 * s, f3 * s);
    ((float4*)out)[(long long)warp * (HF / 4) + lane] = r;
}

// ---------------- tiled SGEMM with f32x2 packed FMA ---------------------------
// C[M,N] = (sum of passes) A @ W^T (+bias)(+relu). W row-major [N,K].
// Tile 128x64, 256 threads; thread computes 8 rows (4 m-pairs) x 4 cols.
// B tile stored duplicated (b,b) per entry, columns permuted so each thread's
// 4 b-pairs are two contiguous 16B loads.
template<bool DUAL, bool RELU_IN, bool RELU_OUT, bool HAS_BIAS>
__global__ void gemm_kernel(const float* __restrict__ A, const float* __restrict__ W,
                            const float* __restrict__ A2, const float* __restrict__ W2,
                            const float* __restrict__ bias, float* __restrict__ C,
                            int M, int N, int K) {
    const int BM = 128, BN = 64, BK = 32;
    __shared__ float As[BK][BM];   // 16 KB, m contiguous
    __shared__ ull   Bsd[BK][BN];  // 16 KB, duplicated pairs, permuted columns
    int tid = threadIdx.x;
    int m0 = blockIdx.x * BM;
    int n0 = blockIdx.y * BN;
    int tm = tid >> 4;      // 0..15 -> 8 rows each
    int tn = tid & 15;      // 0..15 -> 4 cols each

    ull acc[4][4];          // [m-pair][col], each packs (row_even, row_odd)
#pragma unroll
    for (int i = 0; i < 4; i++)
#pragma unroll
        for (int j = 0; j < 4; j++) acc[i][j] = 0ull;

    const int passes = DUAL ? 2 : 1;
    for (int p = 0; p < passes; p++) {
        const float* Ap = (DUAL && p) ? A2 : A;
        const float* Wp = (DUAL && p) ? W2 : W;
        for (int k0 = 0; k0 < K; k0 += BK) {
            // A tile (BM x BK): 1024 float4 slots / 256 threads = 4 each
#pragma unroll
            for (int it = 0; it < 4; it++) {
                int f = tid + it * 256;
                int m  = f >> 3;
                int kq = f & 7;
                float4 v = make_float4(0.f, 0.f, 0.f, 0.f);
                if (m0 + m < M)
                    v = *(const float4*)&Ap[(long long)(m0 + m) * K + k0 + kq * 4];
                if (RELU_IN) {
                    v.x = fmaxf(v.x, 0.f); v.y = fmaxf(v.y, 0.f);
                    v.z = fmaxf(v.z, 0.f); v.w = fmaxf(v.w, 0.f);
                }
                As[kq * 4 + 0][m] = v.x;
                As[kq * 4 + 1][m] = v.y;
                As[kq * 4 + 2][m] = v.z;
                As[kq * 4 + 3][m] = v.w;
            }
            // W tile (BN x BK), duplicated + permuted: col nn -> slot
            //   slot = ((nn&3)>>1)*32 + (nn>>2)*2 + (nn&1)
#pragma unroll
            for (int it = 0; it < 2; it++) {
                int f = tid + it * 256;
                int nn = f >> 3;
                int kq = f & 7;
                float4 v = *(const float4*)&Wp[(long long)(n0 + nn) * K + k0 + kq * 4];
                int slot = ((nn & 3) >> 1) * 32 + (nn >> 2) * 2 + (nn & 1);
                Bsd[kq * 4 + 0][slot] = pk2(v.x, v.x);
                Bsd[kq * 4 + 1][slot] = pk2(v.y, v.y);
                Bsd[kq * 4 + 2][slot] = pk2(v.z, v.z);
                Bsd[kq * 4 + 3][slot] = pk2(v.w, v.w);
            }
            __syncthreads();
#pragma unroll
            for (int kk = 0; kk < BK; kk++) {
                ulonglong2 A0 = *(const ulonglong2*)&As[kk][tm * 8];      // pairs 0,1
                ulonglong2 A1 = *(const ulonglong2*)&As[kk][tm * 8 + 4];  // pairs 2,3
                ulonglong2 B0 = *(const ulonglong2*)&Bsd[kk][tn * 2];      // j=0,1
                ulonglong2 B1 = *(const ulonglong2*)&Bsd[kk][32 + tn * 2]; // j=2,3
                FMA2(acc[0][0], A0.x, B0.x, acc[0][0]);
                FMA2(acc[0][1], A0.x, B0.y, acc[0][1]);
                FMA2(acc[0][2], A0.x, B1.x, acc[0][2]);
                FMA2(acc[0][3], A0.x, B1.y, acc[0][3]);
                FMA2(acc[1][0], A0.y, B0.x, acc[1][0]);
                FMA2(acc[1][1], A0.y, B0.y, acc[1][1]);
                FMA2(acc[1][2], A0.y, B1.x, acc[1][2]);
                FMA2(acc[1][3], A0.y, B1.y, acc[1][3]);
                FMA2(acc[2][0], A1.x, B0.x, acc[2][0]);
                FMA2(acc[2][1], A1.x, B0.y, acc[2][1]);
                FMA2(acc[2][2], A1.x, B1.x, acc[2][2]);
                FMA2(acc[2][3], A1.x, B1.y, acc[2][3]);
                FMA2(acc[3][0], A1.y, B0.x, acc[3][0]);
                FMA2(acc[3][1], A1.y, B0.y, acc[3][1]);
                FMA2(acc[3][2], A1.y, B1.x, acc[3][2]);
                FMA2(acc[3][3], A1.y, B1.y, acc[3][3]);
            }
            __syncthreads();
        }
    }

    // Epilogue: unpack m-pairs, build per-row float4, store
#pragma unroll
    for (int mp = 0; mp < 4; mp++) {
        int r0 = m0 + tm * 8 + mp * 2;
        int r1 = r0 + 1;
        float lo[4], hi[4];
#pragma unroll
        for (int j = 0; j < 4; j++) upk2(lo[j], hi[j], acc[mp][j]);
        int nn = n0 + tn * 4;
#pragma unroll
        for (int j = 0; j < 4; j++) {
            float b = HAS_BIAS ? bias[nn + j] : 0.f;
            lo[j] += b; hi[j] += b;
            if (RELU_OUT) { lo[j] = fmaxf(lo[j], 0.f); hi[j] = fmaxf(hi[j], 0.f); }
        }
        if (r0 < M)
            *(float4*)&C[(long long)r0 * N + nn] = make_float4(lo[0], lo[1], lo[2], lo[3]);
        if (r1 < M)
            *(float4*)&C[(long long)r1 * N + nn] = make_float4(hi[0], hi[1], hi[2], hi[3]);
    }
}

// ---------------- launch ------------------------------------------------------
extern "C" void kernel_launch(void* const* d_in, const int* in_sizes, int n_in,
                              void* d_out, int out_size) {
    const float* x     = (const float*)d_in[0];
    const void*  ei    = d_in[1];
    const float* W_lin = (const float*)d_in[2];
    const float* b_lin = (const float*)d_in[3];
    const float* Wl1   = (const float*)d_in[4];
    const float* bl1   = (const float*)d_in[5];
    const float* Wr1   = (const float*)d_in[6];
    const float* Wl2   = (const float*)d_in[7];
    const float* bl2   = (const float*)d_in[8];
    const float* Wr2   = (const float*)d_in[9];
    const float* W_cls = (const float*)d_in[10];
    float* out = (float*)d_out;

    int n_nodes = in_sizes[0] / IN_F;
    int E       = in_sizes[1] / 2;

    float *h0, *h1, *h2, *mean;
    int *cnt;
    cudaGetSymbolAddress((void**)&h0,   g_h0);
    cudaGetSymbolAddress((void**)&h1,   g_h1);
    cudaGetSymbolAddress((void**)&h2,   g_h2);
    cudaGetSymbolAddress((void**)&mean, g_mean);
    cudaGetSymbolAddress((void**)&cnt,  g_cnt);

    int nb_edges = (E + 255) / 256;
    dim3 gH((n_nodes + 127) / 128, HF / 64);   // N=128 -> y=2
    dim3 gC((n_nodes + 127) / 128, NC / 64);   // N=64  -> y=1

    // Build padded CSR: memset counters, detect dtype, scatter
    cudaMemsetAsync(cnt, 0, n_nodes * sizeof(int));
    detect_kernel<<<1, 256>>>(ei, (long long)2 * E, n_nodes);
    scatter_kernel<<<nb_edges, 256>>>(ei, E);

    // h0 = relu(x @ W_lin^T + b_lin)
    gemm_kernel<false, false, true, true><<<gH, 256>>>(
        x, W_lin, nullptr, nullptr, b_lin, h0, n_nodes, HF, IN_F);

    // sage1: mean-agg(h0) -> mean; h1 = mean @ Wl1^T + bl1 + h0 @ Wr1^T
    agg_kernel<<<(n_nodes + 7) / 8, 256>>>(h0, mean, n_nodes);
    gemm_kernel<true, false, false, true><<<gH, 256>>>(
        mean, Wl1, h0, Wr1, bl1, h1, n_nodes, HF, HF);

    // sage2: mean-agg(h1) -> mean; h2 = mean @ Wl2^T + bl2 + h1 @ Wr2^T
    agg_kernel<<<(n_nodes + 7) / 8, 256>>>(h1, mean, n_nodes);
    gemm_kernel<true, false, false, true><<<gH, 256>>>(
        mean, Wl2, h1, Wr2, bl2, h2, n_nodes, HF, HF);

    // out = relu(h2) @ W_cls^T
    gemm_kernel<false, true, false, false><<<gC, 256>>>(
        h2, W_cls, nullptr, nullptr, nullptr, out, n_nodes, NC, HF);
}

// round 4
// speedup vs baseline: 1.0833x; 1.0833x over previous
#include <cuda_runtime.h>
#include <cuda_bf16.h>

#define IN_F 256
#define HF   128
#define NC   64
#define MAX_NODES 10000
#define MAX_EDGES 640000
#define PAD 192   // max supported degree; Poisson(64) tail at 192 is ~1e-60

typedef unsigned long long ull;

#define ADD2(d, a, b) \
    asm("add.rn.f32x2 %0, %1, %2;" : "=l"(d) : "l"(a), "l"(b))
__device__ __forceinline__ void upk2(float& lo, float& hi, ull v) {
    asm("mov.b64 {%0, %1}, %2;" : "=f"(lo), "=f"(hi) : "l"(v));
}

// ---------------- scratch (static device globals; no allocation) -------------
__device__ float g_h0[MAX_NODES * HF];
__device__ float g_h1[MAX_NODES * HF];
__device__ float g_h2[MAX_NODES * HF];
__device__ float g_mean[MAX_NODES * HF];
__device__ int   g_cnt[MAX_NODES];
__device__ int   g_csr[MAX_NODES * PAD];
__device__ int   g_is64;

// ---------------- dtype detect -----------------------------------------------
__global__ void detect_kernel(const void* ei, long long total_elems, int n_nodes) {
    if (threadIdx.x == 0 && blockIdx.x == 0) g_is64 = 1;
    __threadfence();
    const long long* p = (const long long*)ei;
    long long nsamp = total_elems < 4096 ? total_elems : 4096;
    for (long long i = threadIdx.x; i < nsamp; i += blockDim.x) {
        long long v = p[i];
        if (v < 0 || v >= (long long)n_nodes) { g_is64 = 0; break; }
    }
}

// ---------------- padded-CSR scatter (one pass, no scan) ----------------------
__global__ void scatter_kernel(const void* ei, int E) {
    int e = blockIdx.x * blockDim.x + threadIdx.x;
    if (e >= E) return;
    int is64 = g_is64;
    int src, dst;
    if (is64) {
        src = (int)((const long long*)ei)[e];
        dst = (int)((const long long*)ei)[(long long)E + e];
    } else {
        src = ((const int*)ei)[e];
        dst = ((const int*)ei)[E + e];
    }
    int pos = atomicAdd(&g_cnt[dst], 1);
    if (pos < PAD) g_csr[dst * PAD + pos] = src;
}

// ---------------- mean aggregation (pull over padded CSR, warp per node) ------
__global__ void __launch_bounds__(256, 4)
agg_kernel(const float* __restrict__ h, float* __restrict__ out, int n) {
    int warp = (blockIdx.x * blockDim.x + threadIdx.x) >> 5;
    int lane = threadIdx.x & 31;
    if (warp >= n) return;
    int deg = g_cnt[warp];
    int end = deg < PAD ? deg : PAD;
    const int* lst = &g_csr[warp * PAD];
    const ulonglong2* hb = (const ulonglong2*)h;

    ull a0p0 = 0, a0p1 = 0, a1p0 = 0, a1p1 = 0;
    ull a2p0 = 0, a2p1 = 0, a3p0 = 0, a3p1 = 0;

    int e = 0;
    for (; e + 3 < end; e += 4) {
        int j0 = lst[e], j1 = lst[e + 1], j2 = lst[e + 2], j3 = lst[e + 3];
        ulonglong2 v0 = hb[(long long)j0 * (HF / 4) + lane];
        ulonglong2 v1 = hb[(long long)j1 * (HF / 4) + lane];
        ulonglong2 v2 = hb[(long long)j2 * (HF / 4) + lane];
        ulonglong2 v3 = hb[(long long)j3 * (HF / 4) + lane];
        ADD2(a0p0, a0p0, v0.x); ADD2(a0p1, a0p1, v0.y);
        ADD2(a1p0, a1p0, v1.x); ADD2(a1p1, a1p1, v1.y);
        ADD2(a2p0, a2p0, v2.x); ADD2(a2p1, a2p1, v2.y);
        ADD2(a3p0, a3p0, v3.x); ADD2(a3p1, a3p1, v3.y);
    }
    for (; e < end; e++) {
        int j0 = lst[e];
        ulonglong2 v0 = hb[(long long)j0 * (HF / 4) + lane];
        ADD2(a0p0, a0p0, v0.x); ADD2(a0p1, a0p1, v0.y);
    }
    ADD2(a0p0, a0p0, a1p0); ADD2(a0p1, a0p1, a1p1);
    ADD2(a2p0, a2p0, a3p0); ADD2(a2p1, a2p1, a3p1);
    ADD2(a0p0, a0p0, a2p0); ADD2(a0p1, a0p1, a2p1);

    float s = 1.0f / (float)(deg > 1 ? deg : 1);
    float f0, f1, f2, f3;
    upk2(f0, f1, a0p0);
    upk2(f2, f3, a0p1);
    float4 r = make_float4(f0 * s, f1 * s, f2 * s, f3 * s);
    ((float4*)out)[(long long)warp * (HF / 4) + lane] = r;
}

// ---------------- tiled SGEMM (scalar FFMA, small tiles for wave balance) -----
// C[M,N] = (sum of passes) A @ W^T (+bias)(+relu). W row-major [N,K].
// Tile BM x 64, BK=32, 256 threads; thread computes RM=BM/16 rows x 4 cols.
template<int BM, bool DUAL, bool RELU_IN, bool RELU_OUT, bool HAS_BIAS>
__global__ void __launch_bounds__(256)
gemm_kernel(const float* __restrict__ A, const float* __restrict__ W,
            const float* __restrict__ A2, const float* __restrict__ W2,
            const float* __restrict__ bias, float* __restrict__ C,
            int M, int N, int K) {
    const int BN = 64, BK = 32;
    const int RM = BM / 16;
    __shared__ float As[BK][BM];
    __shared__ float Bs[BK][BN];
    int tid = threadIdx.x;
    int m0 = blockIdx.x * BM;
    int n0 = blockIdx.y * BN;
    int tm = tid >> 4;      // 0..15 -> RM rows each
    int tn = tid & 15;      // 0..15 -> 4 cols each

    float acc[RM][4];
#pragma unroll
    for (int i = 0; i < RM; i++)
#pragma unroll
        for (int j = 0; j < 4; j++) acc[i][j] = 0.f;

    const int passes = DUAL ? 2 : 1;
    for (int p = 0; p < passes; p++) {
        const float* Ap = (DUAL && p) ? A2 : A;
        const float* Wp = (DUAL && p) ? W2 : W;
        for (int k0 = 0; k0 < K; k0 += BK) {
            // A tile (BM x BK): BM*8 float4 slots
            for (int f = tid; f < BM * 8; f += 256) {
                int m  = f >> 3;
                int kq = f & 7;
                float4 v = make_float4(0.f, 0.f, 0.f, 0.f);
                if (m0 + m < M)
                    v = *(const float4*)&Ap[(long long)(m0 + m) * K + k0 + kq * 4];
                if (RELU_IN) {
                    v.x = fmaxf(v.x, 0.f); v.y = fmaxf(v.y, 0.f);
                    v.z = fmaxf(v.z, 0.f); v.w = fmaxf(v.w, 0.f);
                }
                As[kq * 4 + 0][m] = v.x;
                As[kq * 4 + 1][m] = v.y;
                As[kq * 4 + 2][m] = v.z;
                As[kq * 4 + 3][m] = v.w;
            }
            // W tile (BN x BK): 512 float4 slots -> 2 iters
#pragma unroll
            for (int it = 0; it < 2; it++) {
                int f = tid + it * 256;
                int nn = f >> 3;
                int kq = f & 7;
                float4 v = *(const float4*)&Wp[(long long)(n0 + nn) * K + k0 + kq * 4];
                Bs[kq * 4 + 0][nn] = v.x;
                Bs[kq * 4 + 1][nn] = v.y;
                Bs[kq * 4 + 2][nn] = v.z;
                Bs[kq * 4 + 3][nn] = v.w;
            }
            __syncthreads();
#pragma unroll
            for (int kk = 0; kk < BK; kk++) {
                float a[RM];
#pragma unroll
                for (int i = 0; i < RM; i++) a[i] = As[kk][tm * RM + i];
                float4 b = *(const float4*)&Bs[kk][tn * 4];
#pragma unroll
                for (int i = 0; i < RM; i++) {
                    acc[i][0] += a[i] * b.x;
                    acc[i][1] += a[i] * b.y;
                    acc[i][2] += a[i] * b.z;
                    acc[i][3] += a[i] * b.w;
                }
            }
            __syncthreads();
        }
    }

#pragma unroll
    for (int i = 0; i < RM; i++) {
        int m = m0 + tm * RM + i;
        if (m >= M) continue;
        int nn = n0 + tn * 4;
        float v0 = acc[i][0], v1 = acc[i][1], v2 = acc[i][2], v3 = acc[i][3];
        if (HAS_BIAS) {
            v0 += bias[nn + 0]; v1 += bias[nn + 1];
            v2 += bias[nn + 2]; v3 += bias[nn + 3];
        }
        if (RELU_OUT) {
            v0 = fmaxf(v0, 0.f); v1 = fmaxf(v1, 0.f);
            v2 = fmaxf(v2, 0.f); v3 = fmaxf(v3, 0.f);
        }
        *(float4*)&C[(long long)m * N + nn] = make_float4(v0, v1, v2, v3);
    }
}

// ---------------- launch ------------------------------------------------------
extern "C" void kernel_launch(void* const* d_in, const int* in_sizes, int n_in,
                              void* d_out, int out_size) {
    const float* x     = (const float*)d_in[0];
    const void*  ei    = d_in[1];
    const float* W_lin = (const float*)d_in[2];
    const float* b_lin = (const float*)d_in[3];
    const float* Wl1   = (const float*)d_in[4];
    const float* bl1   = (const float*)d_in[5];
    const float* Wr1   = (const float*)d_in[6];
    const float* Wl2   = (const float*)d_in[7];
    const float* bl2   = (const float*)d_in[8];
    const float* Wr2   = (const float*)d_in[9];
    const float* W_cls = (const float*)d_in[10];
    float* out = (float*)d_out;

    int n_nodes = in_sizes[0] / IN_F;
    int E       = in_sizes[1] / 2;

    float *h0, *h1, *h2, *mean;
    int *cnt;
    cudaGetSymbolAddress((void**)&h0,   g_h0);
    cudaGetSymbolAddress((void**)&h1,   g_h1);
    cudaGetSymbolAddress((void**)&h2,   g_h2);
    cudaGetSymbolAddress((void**)&mean, g_mean);
    cudaGetSymbolAddress((void**)&cnt,  g_cnt);

    int nb_edges = (E + 255) / 256;
    const int BM = 48;   // 209x2 = 418 blocks -> ~1.06x wave imbalance
    dim3 gH((n_nodes + BM - 1) / BM, HF / 64);   // N=128 -> y=2
    dim3 gC((n_nodes + BM - 1) / BM, NC / 64);   // N=64  -> y=1

    // Build padded CSR: memset counters, detect dtype, scatter
    cudaMemsetAsync(cnt, 0, n_nodes * sizeof(int));
    detect_kernel<<<1, 256>>>(ei, (long long)2 * E, n_nodes);
    scatter_kernel<<<nb_edges, 256>>>(ei, E);

    // h0 = relu(x @ W_lin^T + b_lin)
    gemm_kernel<BM, false, false, true, true><<<gH, 256>>>(
        x, W_lin, nullptr, nullptr, b_lin, h0, n_nodes, HF, IN_F);

    // sage1: mean-agg(h0) -> mean; h1 = mean @ Wl1^T + bl1 + h0 @ Wr1^T
    agg_kernel<<<(n_nodes + 7) / 8, 256>>>(h0, mean, n_nodes);
    gemm_kernel<BM, true, false, false, true><<<gH, 256>>>(
        mean, Wl1, h0, Wr1, bl1, h1, n_nodes, HF, HF);

    // sage2: mean-agg(h1) -> mean; h2 = mean @ Wl2^T + bl2 + h1 @ Wr2^T
    agg_kernel<<<(n_nodes + 7) / 8, 256>>>(h1, mean, n_nodes);
    gemm_kernel<BM, true, false, false, true><<<gH, 256>>>(
        mean, Wl2, h1, Wr2, bl2, h2, n_nodes, HF, HF);

    // out = relu(h2) @ W_cls^T
    gemm_kernel<BM, false, true, false, false><<<gC, 256>>>(
        h2, W_cls, nullptr, nullptr, nullptr, out, n_nodes, NC, HF);
}

// round 5
// speedup vs baseline: 1.0947x; 1.0105x over previous
#include <cuda_runtime.h>
#include <cuda_bf16.h>

#define IN_F 256
#define HF   128
#define NC   64
#define MAX_NODES 10000
#define MAX_EDGES 640000
#define PAD 192   // max supported degree; Poisson(64) tail at 192 is ~1e-60
#define BMF 24    // fused tile: nodes per block -> 417 blocks (1.06x balance)

typedef unsigned long long ull;
typedef long long ll;

#define ADD2(d, a, b) \
    asm("add.rn.f32x2 %0, %1, %2;" : "=l"(d) : "l"(a), "l"(b))
__device__ __forceinline__ void upk2(float& lo, float& hi, ull v) {
    asm("mov.b64 {%0, %1}, %2;" : "=f"(lo), "=f"(hi) : "l"(v));
}

// ---------------- scratch (static device globals; no allocation) -------------
__device__ float g_h0[MAX_NODES * HF];
__device__ float g_h1[MAX_NODES * HF];
__device__ int   g_cnt[MAX_NODES];
__device__ int   g_csr[MAX_NODES * PAD];
__device__ int   g_is64;

// ---------------- dtype detect -----------------------------------------------
__global__ void detect_kernel(const void* ei, long long total_elems, int n_nodes) {
    if (threadIdx.x == 0 && blockIdx.x == 0) g_is64 = 1;
    __threadfence();
    const long long* p = (const long long*)ei;
    long long nsamp = total_elems < 4096 ? total_elems : 4096;
    for (long long i = threadIdx.x; i < nsamp; i += blockDim.x) {
        long long v = p[i];
        if (v < 0 || v >= (long long)n_nodes) { g_is64 = 0; break; }
    }
}

// ---------------- padded-CSR scatter (one pass, no scan) ----------------------
__global__ void scatter_kernel(const void* ei, int E) {
    int e = blockIdx.x * blockDim.x + threadIdx.x;
    if (e >= E) return;
    int is64 = g_is64;
    int src, dst;
    if (is64) {
        src = (int)((const long long*)ei)[e];
        dst = (int)((const long long*)ei)[(long long)E + e];
    } else {
        src = ((const int*)ei)[e];
        dst = ((const int*)ei)[E + e];
    }
    int pos = atomicAdd(&g_cnt[dst], 1);
    if (pos < PAD) g_csr[dst * PAD + pos] = src;
}

// ---------------- fused SAGE layer: agg (smem) + dual GEMM (+ fused classifier)
// hin: [M, HF] features. Computes h_out = mean_agg(hin) @ Wl^T + bl + hin @ Wr^T.
// If CLS: additionally out = relu(h_out) @ Wc^T, h_out not written to gmem.
template<bool CLS>
__global__ void __launch_bounds__(256)
fused_sage(const float* __restrict__ hin,
           const float* __restrict__ Wl, const float* __restrict__ bl,
           const float* __restrict__ Wr, const float* __restrict__ Wc,
           float* __restrict__ hout, int M) {
    __shared__ float MeanT[HF][BMF + 1];  // [k][m] transposed mean; reused as H2T
    __shared__ float Bs[32][HF];          // W chunk, [kk][n]
    __shared__ float As[32][BMF];         // hin chunk for Wr pass, [kk][m]

    int tid  = threadIdx.x;
    int wid  = tid >> 5;      // warp 0..7
    int lane = tid & 31;
    int m0   = blockIdx.x * BMF;

    // ---- Phase A: mean aggregation for this block's nodes -> MeanT ----------
    {
        const ulonglong2* hb = (const ulonglong2*)hin;  // 16B units; row = 32 units
        for (int i = wid; i < BMF; i += 8) {
            int node = m0 + i;
            if (node >= M) continue;
            int deg = g_cnt[node];
            int end = deg < PAD ? deg : PAD;
            const int* lst = &g_csr[node * PAD];
            ull a0 = 0, a1 = 0, b0 = 0, b1 = 0, c0 = 0, c1 = 0, d0 = 0, d1 = 0;
            int e = 0;
            for (; e + 3 < end; e += 4) {
                int j0 = lst[e], j1 = lst[e + 1], j2 = lst[e + 2], j3 = lst[e + 3];
                ulonglong2 v0 = hb[(ll)j0 * 32 + lane];
                ulonglong2 v1 = hb[(ll)j1 * 32 + lane];
                ulonglong2 v2 = hb[(ll)j2 * 32 + lane];
                ulonglong2 v3 = hb[(ll)j3 * 32 + lane];
                ADD2(a0, a0, v0.x); ADD2(a1, a1, v0.y);
                ADD2(b0, b0, v1.x); ADD2(b1, b1, v1.y);
                ADD2(c0, c0, v2.x); ADD2(c1, c1, v2.y);
                ADD2(d0, d0, v3.x); ADD2(d1, d1, v3.y);
            }
            for (; e < end; e++) {
                int j0 = lst[e];
                ulonglong2 v0 = hb[(ll)j0 * 32 + lane];
                ADD2(a0, a0, v0.x); ADD2(a1, a1, v0.y);
            }
            ADD2(a0, a0, b0); ADD2(a1, a1, b1);
            ADD2(c0, c0, d0); ADD2(c1, c1, d1);
            ADD2(a0, a0, c0); ADD2(a1, a1, c1);
            float s = 1.0f / (float)(deg > 1 ? deg : 1);
            float f0, f1, f2, f3;
            upk2(f0, f1, a0);
            upk2(f2, f3, a1);
            MeanT[lane * 4 + 0][i] = f0 * s;
            MeanT[lane * 4 + 1][i] = f1 * s;
            MeanT[lane * 4 + 2][i] = f2 * s;
            MeanT[lane * 4 + 3][i] = f3 * s;
        }
    }
    __syncthreads();

    // ---- Phase B: acc = MeanT @ Wl^T + hin_rows @ Wr^T -----------------------
    int tm = wid;   // rows tm*3 .. tm*3+2
    int tn = lane;  // cols tn*4 .. tn*4+3
    float acc[3][4];
#pragma unroll
    for (int i = 0; i < 3; i++)
#pragma unroll
        for (int j = 0; j < 4; j++) acc[i][j] = 0.f;

    for (int pass = 0; pass < 2; pass++) {
        const float* Wp = pass ? Wr : Wl;
        for (int k0 = 0; k0 < HF; k0 += 32) {
            if (pass) {
                // As[kk][m] <- hin rows (transposed), 24*8=192 float4 slots
                if (tid < BMF * 8) {
                    int m = tid >> 3, kq = tid & 7;
                    float4 v = make_float4(0.f, 0.f, 0.f, 0.f);
                    if (m0 + m < M)
                        v = *(const float4*)&hin[(ll)(m0 + m) * HF + k0 + kq * 4];
                    As[kq * 4 + 0][m] = v.x;
                    As[kq * 4 + 1][m] = v.y;
                    As[kq * 4 + 2][m] = v.z;
                    As[kq * 4 + 3][m] = v.w;
                }
            }
            // Bs[kk][nn] <- W chunk, 128*8 = 1024 float4 slots / 256 thr = 4 each
#pragma unroll
            for (int it = 0; it < 4; it++) {
                int f = tid + it * 256;
                int nn = f >> 3, kq = f & 7;
                float4 v = *(const float4*)&Wp[(ll)nn * HF + k0 + kq * 4];
                Bs[kq * 4 + 0][nn] = v.x;
                Bs[kq * 4 + 1][nn] = v.y;
                Bs[kq * 4 + 2][nn] = v.z;
                Bs[kq * 4 + 3][nn] = v.w;
            }
            __syncthreads();
#pragma unroll
            for (int kk = 0; kk < 32; kk++) {
                float x0, x1, x2;
                if (pass) {
                    x0 = As[kk][tm * 3 + 0];
                    x1 = As[kk][tm * 3 + 1];
                    x2 = As[kk][tm * 3 + 2];
                } else {
                    x0 = MeanT[k0 + kk][tm * 3 + 0];
                    x1 = MeanT[k0 + kk][tm * 3 + 1];
                    x2 = MeanT[k0 + kk][tm * 3 + 2];
                }
                float4 b = *(const float4*)&Bs[kk][tn * 4];
                acc[0][0] += x0 * b.x; acc[0][1] += x0 * b.y; acc[0][2] += x0 * b.z; acc[0][3] += x0 * b.w;
                acc[1][0] += x1 * b.x; acc[1][1] += x1 * b.y; acc[1][2] += x1 * b.z; acc[1][3] += x1 * b.w;
                acc[2][0] += x2 * b.x; acc[2][1] += x2 * b.y; acc[2][2] += x2 * b.z; acc[2][3] += x2 * b.w;
            }
            __syncthreads();
        }
    }

    if (!CLS) {
        // h_out = acc + bl
        float4 bb = *(const float4*)&bl[tn * 4];
#pragma unroll
        for (int i = 0; i < 3; i++) {
            int m = m0 + tm * 3 + i;
            if (m >= M) continue;
            *(float4*)&hout[(ll)m * HF + tn * 4] =
                make_float4(acc[i][0] + bb.x, acc[i][1] + bb.y,
                            acc[i][2] + bb.z, acc[i][3] + bb.w);
        }
    } else {
        // h2 = relu(acc + bl) -> H2T (reusing MeanT), then out = H2T^T @ Wc^T
        float4 bb = *(const float4*)&bl[tn * 4];
#pragma unroll
        for (int i = 0; i < 3; i++) {
#pragma unroll
            for (int j = 0; j < 4; j++) {
                float bv = (j == 0) ? bb.x : (j == 1) ? bb.y : (j == 2) ? bb.z : bb.w;
                MeanT[tn * 4 + j][tm * 3 + i] = fmaxf(acc[i][j] + bv, 0.f);
            }
        }
        __syncthreads();
        float acc2[3][2];
#pragma unroll
        for (int i = 0; i < 3; i++) { acc2[i][0] = 0.f; acc2[i][1] = 0.f; }
        for (int k0 = 0; k0 < HF; k0 += 32) {
            // Bs[kk][nn] <- W_cls chunk, 64*8 = 512 slots / 256 thr = 2 each
#pragma unroll
            for (int it = 0; it < 2; it++) {
                int f = tid + it * 256;
                int nn = f >> 3, kq = f & 7;
                float4 v = *(const float4*)&Wc[(ll)nn * HF + k0 + kq * 4];
                Bs[kq * 4 + 0][nn] = v.x;
                Bs[kq * 4 + 1][nn] = v.y;
                Bs[kq * 4 + 2][nn] = v.z;
                Bs[kq * 4 + 3][nn] = v.w;
            }
            __syncthreads();
#pragma unroll
            for (int kk = 0; kk < 32; kk++) {
                float x0 = MeanT[k0 + kk][tm * 3 + 0];
                float x1 = MeanT[k0 + kk][tm * 3 + 1];
                float x2 = MeanT[k0 + kk][tm * 3 + 2];
                float b0 = Bs[kk][tn * 2 + 0];
                float b1 = Bs[kk][tn * 2 + 1];
                acc2[0][0] += x0 * b0; acc2[0][1] += x0 * b1;
                acc2[1][0] += x1 * b0; acc2[1][1] += x1 * b1;
                acc2[2][0] += x2 * b0; acc2[2][1] += x2 * b1;
            }
            __syncthreads();
        }
#pragma unroll
        for (int i = 0; i < 3; i++) {
            int m = m0 + tm * 3 + i;
            if (m >= M) continue;
            *(float2*)&hout[(ll)m * NC + tn * 2] = make_float2(acc2[i][0], acc2[i][1]);
        }
    }
}

// ---------------- input projection SGEMM (scalar FFMA, 48x64 tiles) -----------
__global__ void __launch_bounds__(256)
proj_kernel(const float* __restrict__ A, const float* __restrict__ W,
            const float* __restrict__ bias, float* __restrict__ C,
            int M, int N, int K) {
    const int BM = 48, BN = 64, BK = 32, RM = 3;
    __shared__ float As[BK][BM];
    __shared__ float Bs[BK][BN];
    int tid = threadIdx.x;
    int m0 = blockIdx.x * BM;
    int n0 = blockIdx.y * BN;
    int tm = tid >> 4;
    int tn = tid & 15;

    float acc[RM][4];
#pragma unroll
    for (int i = 0; i < RM; i++)
#pragma unroll
        for (int j = 0; j < 4; j++) acc[i][j] = 0.f;

    for (int k0 = 0; k0 < K; k0 += BK) {
        for (int f = tid; f < BM * 8; f += 256) {
            int m = f >> 3, kq = f & 7;
            float4 v = make_float4(0.f, 0.f, 0.f, 0.f);
            if (m0 + m < M)
                v = *(const float4*)&A[(ll)(m0 + m) * K + k0 + kq * 4];
            As[kq * 4 + 0][m] = v.x;
            As[kq * 4 + 1][m] = v.y;
            As[kq * 4 + 2][m] = v.z;
            As[kq * 4 + 3][m] = v.w;
        }
#pragma unroll
        for (int it = 0; it < 2; it++) {
            int f = tid + it * 256;
            int nn = f >> 3, kq = f & 7;
            float4 v = *(const float4*)&W[(ll)(n0 + nn) * K + k0 + kq * 4];
            Bs[kq * 4 + 0][nn] = v.x;
            Bs[kq * 4 + 1][nn] = v.y;
            Bs[kq * 4 + 2][nn] = v.z;
            Bs[kq * 4 + 3][nn] = v.w;
        }
        __syncthreads();
#pragma unroll
        for (int kk = 0; kk < BK; kk++) {
            float a0 = As[kk][tm * RM + 0];
            float a1 = As[kk][tm * RM + 1];
            float a2 = As[kk][tm * RM + 2];
            float4 b = *(const float4*)&Bs[kk][tn * 4];
            acc[0][0] += a0 * b.x; acc[0][1] += a0 * b.y; acc[0][2] += a0 * b.z; acc[0][3] += a0 * b.w;
            acc[1][0] += a1 * b.x; acc[1][1] += a1 * b.y; acc[1][2] += a1 * b.z; acc[1][3] += a1 * b.w;
            acc[2][0] += a2 * b.x; acc[2][1] += a2 * b.y; acc[2][2] += a2 * b.z; acc[2][3] += a2 * b.w;
        }
        __syncthreads();
    }

#pragma unroll
    for (int i = 0; i < RM; i++) {
        int m = m0 + tm * RM + i;
        if (m >= M) continue;
        int nn = n0 + tn * 4;
        float v0 = acc[i][0] + bias[nn + 0];
        float v1 = acc[i][1] + bias[nn + 1];
        float v2 = acc[i][2] + bias[nn + 2];
        float v3 = acc[i][3] + bias[nn + 3];
        v0 = fmaxf(v0, 0.f); v1 = fmaxf(v1, 0.f);
        v2 = fmaxf(v2, 0.f); v3 = fmaxf(v3, 0.f);
        *(float4*)&C[(ll)m * N + nn] = make_float4(v0, v1, v2, v3);
    }
}

// ---------------- launch ------------------------------------------------------
extern "C" void kernel_launch(void* const* d_in, const int* in_sizes, int n_in,
                              void* d_out, int out_size) {
    const float* x     = (const float*)d_in[0];
    const void*  ei    = d_in[1];
    const float* W_lin = (const float*)d_in[2];
    const float* b_lin = (const float*)d_in[3];
    const float* Wl1   = (const float*)d_in[4];
    const float* bl1   = (const float*)d_in[5];
    const float* Wr1   = (const float*)d_in[6];
    const float* Wl2   = (const float*)d_in[7];
    const float* bl2   = (const float*)d_in[8];
    const float* Wr2   = (const float*)d_in[9];
    const float* W_cls = (const float*)d_in[10];
    float* out = (float*)d_out;

    int n_nodes = in_sizes[0] / IN_F;
    int E       = in_sizes[1] / 2;

    float *h0, *h1;
    int *cnt;
    cudaGetSymbolAddress((void**)&h0,  g_h0);
    cudaGetSymbolAddress((void**)&h1,  g_h1);
    cudaGetSymbolAddress((void**)&cnt, g_cnt);

    int nb_edges = (E + 255) / 256;
    int nb_fused = (n_nodes + BMF - 1) / BMF;        // 417 blocks
    dim3 gP((n_nodes + 47) / 48, HF / 64);           // proj: 209 x 2

    // Build padded CSR: memset counters, detect dtype, scatter
    cudaMemsetAsync(cnt, 0, n_nodes * sizeof(int));
    detect_kernel<<<1, 256>>>(ei, (long long)2 * E, n_nodes);
    scatter_kernel<<<nb_edges, 256>>>(ei, E);

    // h0 = relu(x @ W_lin^T + b_lin)
    proj_kernel<<<gP, 256>>>(x, W_lin, b_lin, h0, n_nodes, HF, IN_F);

    // sage1 fused: h1 = mean(h0) @ Wl1^T + bl1 + h0 @ Wr1^T
    fused_sage<false><<<nb_fused, 256>>>(h0, Wl1, bl1, Wr1, nullptr, h1, n_nodes);

    // sage2 + classifier fused: out = relu(mean(h1)@Wl2^T + bl2 + h1@Wr2^T) @ W_cls^T
    fused_sage<true><<<nb_fused, 256>>>(h1, Wl2, bl2, Wr2, W_cls, out, n_nodes);
}

// round 6
// speedup vs baseline: 1.7290x; 1.5795x over previous
#include <cuda_runtime.h>
#include <cuda_bf16.h>
#include <stdint.h>

#define IN_F 256
#define HF   128
#define NC   64
#define MAX_NODES 10000
#define MAX_EDGES 640000
#define PAD 192   // max supported degree; Poisson(64) tail at 192 is ~1e-60

typedef unsigned long long ull;
typedef long long ll;

#define ADD2(d, a, b) \
    asm("add.rn.f32x2 %0, %1, %2;" : "=l"(d) : "l"(a), "l"(b))
__device__ __forceinline__ void upk2(float& lo, float& hi, ull v) {
    asm("mov.b64 {%0, %1}, %2;" : "=f"(lo), "=f"(hi) : "l"(v));
}

// ---------------- scratch (static device globals; no allocation) -------------
__device__ float g_h0[MAX_NODES * HF];
__device__ float g_h1[MAX_NODES * HF];
__device__ float g_h2[MAX_NODES * HF];
__device__ float g_mean[MAX_NODES * HF];
__device__ int   g_cnt[MAX_NODES];
__device__ int   g_csr[MAX_NODES * PAD];
__device__ int   g_is64;

// Persistent split-bf16 weights
#define OFF_LIN 0
#define OFF_L1  32768
#define OFF_R1  49152
#define OFF_L2  65536
#define OFF_R2  81920
#define OFF_CLS 98304
#define TOTW    106496
__device__ __nv_bfloat16 g_Whi[TOTW];
__device__ __nv_bfloat16 g_Wlo[TOTW];

// ---------------- dtype detect -----------------------------------------------
__global__ void detect_kernel(const void* ei, long long total_elems, int n_nodes) {
    if (threadIdx.x == 0 && blockIdx.x == 0) g_is64 = 1;
    __threadfence();
    const long long* p = (const long long*)ei;
    long long nsamp = total_elems < 4096 ? total_elems : 4096;
    for (long long i = threadIdx.x; i < nsamp; i += blockDim.x) {
        long long v = p[i];
        if (v < 0 || v >= (long long)n_nodes) { g_is64 = 0; break; }
    }
}

// ---------------- padded-CSR scatter -------------------------------------------
__global__ void scatter_kernel(const void* ei, int E) {
    int e = blockIdx.x * blockDim.x + threadIdx.x;
    if (e >= E) return;
    int is64 = g_is64;
    int src, dst;
    if (is64) {
        src = (int)((const long long*)ei)[e];
        dst = (int)((const long long*)ei)[(long long)E + e];
    } else {
        src = ((const int*)ei)[e];
        dst = ((const int*)ei)[E + e];
    }
    int pos = atomicAdd(&g_cnt[dst], 1);
    if (pos < PAD) g_csr[dst * PAD + pos] = src;
}

// ---------------- weight split: fp32 -> bf16 hi + bf16 lo ---------------------
__global__ void wsplit_kernel(const float* __restrict__ wlin,
                              const float* __restrict__ wl1, const float* __restrict__ wr1,
                              const float* __restrict__ wl2, const float* __restrict__ wr2,
                              const float* __restrict__ wcls) {
    int i = blockIdx.x * blockDim.x + threadIdx.x;
    if (i >= TOTW) return;
    const float* src; int off;
    if (i < OFF_L1)       { src = wlin; off = OFF_LIN; }
    else if (i < OFF_L2)  { if (i < OFF_R1) { src = wl1; off = OFF_L1; } else { src = wr1; off = OFF_R1; } }
    else if (i < OFF_CLS) { if (i < OFF_R2) { src = wl2; off = OFF_L2; } else { src = wr2; off = OFF_R2; } }
    else                  { src = wcls; off = OFF_CLS; }
    float x = src[i - off];
    __nv_bfloat16 h = __float2bfloat16_rn(x);
    g_Whi[i] = h;
    g_Wlo[i] = __float2bfloat16_rn(x - __bfloat162float(h));
}

// ---------------- mean aggregation (pull over padded CSR, warp per node) ------
__global__ void __launch_bounds__(256, 4)
agg_kernel(const float* __restrict__ h, float* __restrict__ out, int n) {
    int warp = (blockIdx.x * blockDim.x + threadIdx.x) >> 5;
    int lane = threadIdx.x & 31;
    if (warp >= n) return;
    int deg = g_cnt[warp];
    int end = deg < PAD ? deg : PAD;
    const int* lst = &g_csr[warp * PAD];
    const ulonglong2* hb = (const ulonglong2*)h;

    ull a0 = 0, a1 = 0, b0 = 0, b1 = 0, c0 = 0, c1 = 0, d0 = 0, d1 = 0;
    int e = 0;
    for (; e + 3 < end; e += 4) {
        int j0 = lst[e], j1 = lst[e + 1], j2 = lst[e + 2], j3 = lst[e + 3];
        ulonglong2 v0 = hb[(ll)j0 * 32 + lane];
        ulonglong2 v1 = hb[(ll)j1 * 32 + lane];
        ulonglong2 v2 = hb[(ll)j2 * 32 + lane];
        ulonglong2 v3 = hb[(ll)j3 * 32 + lane];
        ADD2(a0, a0, v0.x); ADD2(a1, a1, v0.y);
        ADD2(b0, b0, v1.x); ADD2(b1, b1, v1.y);
        ADD2(c0, c0, v2.x); ADD2(c1, c1, v2.y);
        ADD2(d0, d0, v3.x); ADD2(d1, d1, v3.y);
    }
    for (; e < end; e++) {
        int j0 = lst[e];
        ulonglong2 v0 = hb[(ll)j0 * 32 + lane];
        ADD2(a0, a0, v0.x); ADD2(a1, a1, v0.y);
    }
    ADD2(a0, a0, b0); ADD2(a1, a1, b1);
    ADD2(c0, c0, d0); ADD2(c1, c1, d1);
    ADD2(a0, a0, c0); ADD2(a1, a1, c1);

    float s = 1.0f / (float)(deg > 1 ? deg : 1);
    float f0, f1, f2, f3;
    upk2(f0, f1, a0);
    upk2(f2, f3, a1);
    float4 r = make_float4(f0 * s, f1 * s, f2 * s, f3 * s);
    ((float4*)out)[(ll)warp * 32 + lane] = r;
}

// ---------------- split-bf16 tensor-core GEMM ---------------------------------
// C[M,BN] = (sum of passes) A_p[M,K] @ W_p[BN,K]^T (+bias)(+relu).
// W provided pre-split (g_Whi/g_Wlo + offset). 3 MMAs per k16: hh + lh + hl.
// Block: 256 thr = 8 warps (2 m x 4 n). Block tile 32 x BN, k-chunk 32.
#define MMA_BF16(c, a0,a1,a2,a3, b0,b1) \
    asm volatile("mma.sync.aligned.m16n8k16.row.col.f32.bf16.bf16.f32 " \
        "{%0,%1,%2,%3}, {%4,%5,%6,%7}, {%8,%9}, {%0,%1,%2,%3};" \
        : "+f"(c[0]), "+f"(c[1]), "+f"(c[2]), "+f"(c[3]) \
        : "r"(a0), "r"(a1), "r"(a2), "r"(a3), "r"(b0), "r"(b1))

__device__ __forceinline__ uint32_t pk_hi(float a, float b, float& ra, float& rb) {
    __nv_bfloat16 ha = __float2bfloat16_rn(a), hb = __float2bfloat16_rn(b);
    ra = a - __bfloat162float(ha);
    rb = b - __bfloat162float(hb);
    return (uint32_t)__bfloat16_as_ushort(ha) | ((uint32_t)__bfloat16_as_ushort(hb) << 16);
}
__device__ __forceinline__ uint32_t pk_lo(float a, float b) {
    return (uint32_t)__bfloat16_as_ushort(__float2bfloat16_rn(a)) |
           ((uint32_t)__bfloat16_as_ushort(__float2bfloat16_rn(b)) << 16);
}

// PADW: 20 u32 (=40 bf16) per row -> conflict-free fragment loads
#define PADW 20

template<int BN, bool DUAL, bool RELU_IN, bool RELU_OUT, bool HAS_BIAS>
__global__ void __launch_bounds__(256)
mma_gemm(const float* __restrict__ A1, const float* __restrict__ A2,
         int woff1, int woff2,
         const float* __restrict__ bias, float* __restrict__ C,
         int M, int K) {
    const int NFRAG = BN / 32;            // n8-frags per warp (warp n-width = BN/4)
    const int WN = BN / 4;
    __shared__ uint32_t As_hi[32 * PADW];
    __shared__ uint32_t As_lo[32 * PADW];
    __shared__ uint32_t Ws_hi[BN * PADW];
    __shared__ uint32_t Ws_lo[BN * PADW];

    int tid  = threadIdx.x;
    int wid  = tid >> 5;
    int lane = tid & 31;
    int g    = lane >> 2;    // 0..7
    int t    = lane & 3;     // 0..3
    int wm   = wid >> 2;     // 0..1
    int wn   = wid & 3;      // 0..3
    int m0   = blockIdx.x * 32;

    float c[NFRAG][4];
#pragma unroll
    for (int i = 0; i < NFRAG; i++)
#pragma unroll
        for (int j = 0; j < 4; j++) c[i][j] = 0.f;

    const int passes = DUAL ? 2 : 1;
    for (int p = 0; p < passes; p++) {
        const float* Ap = p ? A2 : A1;
        const __nv_bfloat16* whi = g_Whi + (p ? woff2 : woff1);
        const __nv_bfloat16* wlo = g_Wlo + (p ? woff2 : woff1);
        for (int k0 = 0; k0 < K; k0 += 32) {
            __syncthreads();   // prior MMAs done reading smem
            // ---- A tile fill + split: 32 rows x 32 k = 256 float4 slots -----
            {
                int m = tid >> 3, kq = tid & 7;
                int gm = m0 + m;
                float4 v = make_float4(0.f, 0.f, 0.f, 0.f);
                if (gm < M)
                    v = *(const float4*)&Ap[(ll)gm * K + k0 + kq * 4];
                if (RELU_IN) {
                    v.x = fmaxf(v.x, 0.f); v.y = fmaxf(v.y, 0.f);
                    v.z = fmaxf(v.z, 0.f); v.w = fmaxf(v.w, 0.f);
                }
                float rx, ry, rz, rw;
                uint32_t h0 = pk_hi(v.x, v.y, rx, ry);
                uint32_t h1 = pk_hi(v.z, v.w, rz, rw);
                As_hi[m * PADW + kq * 2 + 0] = h0;
                As_hi[m * PADW + kq * 2 + 1] = h1;
                As_lo[m * PADW + kq * 2 + 0] = pk_lo(rx, ry);
                As_lo[m * PADW + kq * 2 + 1] = pk_lo(rz, rw);
            }
            // ---- W tile copy (pre-split bf16): BN rows x 32 k as uint2 ------
#pragma unroll
            for (int it = 0; it < BN / 32; it++) {
                int f = tid + it * 256;
                int nn = f >> 3, q = f & 7;     // q*4 bf16 = q*2 u32 offset
                const ll si = (ll)nn * K + k0 + q * 4;
                uint2 vh = *(const uint2*)&whi[si];
                uint2 vl = *(const uint2*)&wlo[si];
                *(uint2*)&Ws_hi[nn * PADW + q * 2] = vh;
                *(uint2*)&Ws_lo[nn * PADW + q * 2] = vl;
            }
            __syncthreads();
            // ---- MMA over the two k16 halves --------------------------------
#pragma unroll
            for (int ko = 0; ko < 2; ko++) {
                int kb = ko * 8;
                int ra = (wm * 16 + g) * PADW + kb + t;
                int rb = (wm * 16 + g + 8) * PADW + kb + t;
                uint32_t ah0 = As_hi[ra],     ah1 = As_hi[rb];
                uint32_t ah2 = As_hi[ra + 4], ah3 = As_hi[rb + 4];
                uint32_t al0 = As_lo[ra],     al1 = As_lo[rb];
                uint32_t al2 = As_lo[ra + 4], al3 = As_lo[rb + 4];
#pragma unroll
                for (int nf = 0; nf < NFRAG; nf++) {
                    int nrow = (wn * WN + nf * 8 + g) * PADW + kb + t;
                    uint32_t bh0 = Ws_hi[nrow], bh1 = Ws_hi[nrow + 4];
                    uint32_t bl0 = Ws_lo[nrow], bl1 = Ws_lo[nrow + 4];
                    MMA_BF16(c[nf], ah0, ah1, ah2, ah3, bh0, bh1);
                    MMA_BF16(c[nf], al0, al1, al2, al3, bh0, bh1);
                    MMA_BF16(c[nf], ah0, ah1, ah2, ah3, bl0, bl1);
                }
            }
        }
    }

    // ---- epilogue ------------------------------------------------------------
    int rowa = m0 + wm * 16 + g;
    int rowb = rowa + 8;
#pragma unroll
    for (int nf = 0; nf < NFRAG; nf++) {
        int n = wn * WN + nf * 8 + 2 * t;
        float v0 = c[nf][0], v1 = c[nf][1], v2 = c[nf][2], v3 = c[nf][3];
        if (HAS_BIAS) {
            float bb0 = bias[n], bb1 = bias[n + 1];
            v0 += bb0; v1 += bb1; v2 += bb0; v3 += bb1;
        }
        if (RELU_OUT) {
            v0 = fmaxf(v0, 0.f); v1 = fmaxf(v1, 0.f);
            v2 = fmaxf(v2, 0.f); v3 = fmaxf(v3, 0.f);
        }
        if (rowa < M) *(float2*)&C[(ll)rowa * BN + n] = make_float2(v0, v1);
        if (rowb < M) *(float2*)&C[(ll)rowb * BN + n] = make_float2(v2, v3);
    }
}

// ---------------- launch ------------------------------------------------------
extern "C" void kernel_launch(void* const* d_in, const int* in_sizes, int n_in,
                              void* d_out, int out_size) {
    const float* x     = (const float*)d_in[0];
    const void*  ei    = d_in[1];
    const float* W_lin = (const float*)d_in[2];
    const float* b_lin = (const float*)d_in[3];
    const float* Wl1   = (const float*)d_in[4];
    const float* bl1   = (const float*)d_in[5];
    const float* Wr1   = (const float*)d_in[6];
    const float* Wl2   = (const float*)d_in[7];
    const float* bl2   = (const float*)d_in[8];
    const float* Wr2   = (const float*)d_in[9];
    const float* W_cls = (const float*)d_in[10];
    float* out = (float*)d_out;

    int n_nodes = in_sizes[0] / IN_F;
    int E       = in_sizes[1] / 2;

    float *h0, *h1, *h2, *mean;
    int *cnt;
    cudaGetSymbolAddress((void**)&h0,   g_h0);
    cudaGetSymbolAddress((void**)&h1,   g_h1);
    cudaGetSymbolAddress((void**)&h2,   g_h2);
    cudaGetSymbolAddress((void**)&mean, g_mean);
    cudaGetSymbolAddress((void**)&cnt,  g_cnt);

    int nb_edges = (E + 255) / 256;
    int nb_gemm  = (n_nodes + 31) / 32;          // 313 blocks

    // Build padded CSR + split weights
    cudaMemsetAsync(cnt, 0, n_nodes * sizeof(int));
    detect_kernel<<<1, 256>>>(ei, (long long)2 * E, n_nodes);
    scatter_kernel<<<nb_edges, 256>>>(ei, E);
    wsplit_kernel<<<(TOTW + 255) / 256, 256>>>(W_lin, Wl1, Wr1, Wl2, Wr2, W_cls);

    // h0 = relu(x @ W_lin^T + b_lin)
    mma_gemm<HF, false, false, true, true><<<nb_gemm, 256>>>(
        x, nullptr, OFF_LIN, 0, b_lin, h0, n_nodes, IN_F);

    // sage1: mean-agg(h0); h1 = mean @ Wl1^T + bl1 + h0 @ Wr1^T
    agg_kernel<<<(n_nodes + 7) / 8, 256>>>(h0, mean, n_nodes);
    mma_gemm<HF, true, false, false, true><<<nb_gemm, 256>>>(
        mean, h0, OFF_L1, OFF_R1, bl1, h1, n_nodes, HF);

    // sage2: mean-agg(h1); h2 = mean @ Wl2^T + bl2 + h1 @ Wr2^T
    agg_kernel<<<(n_nodes + 7) / 8, 256>>>(h1, mean, n_nodes);
    mma_gemm<HF, true, false, false, true><<<nb_gemm, 256>>>(
        mean, h1, OFF_L2, OFF_R2, bl2, h2, n_nodes, HF);

    // out = relu(h2) @ W_cls^T
    mma_gemm<NC, false, true, false, false><<<nb_gemm, 256>>>(
        h2, nullptr, OFF_CLS, 0, nullptr, out, n_nodes, HF);
}